// round 16
// baseline (speedup 1.0000x reference)
#include <cuda_runtime.h>
#include <cuda_fp16.h>
#include <math.h>
#include <stdint.h>

// ---------------- problem constants -----------------------------------------
#define TOK   1024
#define D     1024
#define HQ    2048
#define HEADS 8
#define QD    256
#define HALF  128
#define NK    32
#define DTK   4
#define NEXP  128
#define E     1024
#define O     1024
#define KDIM  1024
#define WSCALE   64.0f        // weight operand pre-scale (keeps fp16 l-planes normal)
#define IWSCALE  (1.0f / 64.0f)

// ---------------- scratch (~33 MB of __device__ globals) ----------------------
__device__ __align__(256) float g_q[TOK * HQ];          // 8MB; high 4MB -> C planes
__device__ __align__(256) float g_eh[TOK * E];          // 4MB dense expert pre-acts
__device__ __align__(256) __half g_hid[2 * TOK * D];    // 4MB  (h,l planes, unscaled)
__device__ __align__(256) __half g_wqT[2 * HQ * D];     // 8MB  (transposed, x64)
__device__ __align__(256) __half g_dwn[2 * E * D];      // 4MB  (x64)
__device__ __align__(256) __half g_upT[2 * O * E];      // 4MB  (transposed, x64)
__device__ float g_sums[QD];
__device__ float g_sqs[QD];
__device__ float g_k0n[NK * HALF];
__device__ float g_k1n[NK * HALF];
__device__ unsigned short g_idx[TOK * NEXP];
__device__ float g_w[TOK * NEXP];

// ---------------- helpers ----------------------------------------------------
__device__ __forceinline__ uint32_t s2u(const void* p) {
    uint32_t r;
    asm("{ .reg .u64 t; cvta.to.shared.u64 t, %1; cvt.u32.u64 %0, t; }"
        : "=r"(r) : "l"(p));
    return r;
}

// ---------------- fp16 2-plane split warp-MMA GEMM (segmented N) --------------
// For n-tile n0: if n0 < n1, C1[m, n0+j] = oscale*sum A@B1^T (+bias);
// else C2[m, n0-n1+j] = oscale*sum A@B2^T. Segments never straddle a tile.
// Proven config: static 48KB smem, depth-2 cp.async, 8 warps (4Mx2N of 32x32),
// 2 CTAs/SM; 3 fp16 passes hh+hl+lh (~22 mantissa bits ~ fp32).
#define P    2
#define NPAS 3
#define BK   32
__global__ __launch_bounds__(256, 2)
void gemm_planes(const __half* __restrict__ A,
                 const __half* __restrict__ B1, const __half* __restrict__ B2,
                 const float* __restrict__ bias,
                 float* __restrict__ C1, float* __restrict__ C2,
                 int n1, int ld1, int ld2,
                 int aPl, int b1Pl, int b2Pl, float oscale)
{
    constexpr int CPR   = BK / 8;            // 4 16B chunks per row per plane
    constexpr int BKB   = BK * 2;            // 64 bytes per row per plane
    constexpr int APL   = 128 * BKB;         // 8KB
    constexpr int BPL   = 64 * BKB;          // 4KB
    constexpr int STAGE = P * (APL + BPL);   // 24KB
    constexpr int NCHA  = P * 128 * CPR;
    constexpr int NCH   = NCHA + P * 64 * CPR;
    constexpr int NIT   = KDIM / BK;         // 32
    constexpr int KT    = BK / 16;           // 2

    __shared__ __align__(1024) char smem[2 * STAGE];   // 48KB static
    const uint32_t sbase = s2u(smem);
    const int tid = threadIdx.x, w = tid >> 5, l = tid & 31;
    const int m0 = blockIdx.y * 128, n0 = blockIdx.x * 64;
    const int wm = (w >> 1) * 32, wn = (w & 1) * 32;

    const bool seg1 = (n0 < n1);
    const __half* Bp = seg1 ? B1 : B2;
    const int brow0 = seg1 ? n0 : (n0 - n1);
    const int bPl = seg1 ? b1Pl : b2Pl;

    float acc[2][4][4];
    #pragma unroll
    for (int a = 0; a < 2; a++)
        #pragma unroll
        for (int b = 0; b < 4; b++)
            #pragma unroll
            for (int c = 0; c < 4; c++) acc[a][b][c] = 0.f;

    auto swz = [](int c, int r) -> int { return c ^ ((r >> 1) & 3); };

    auto issue = [&](int it) {
        const int s = it & 1;
        const int k0 = it * BK;
        const uint32_t sb0 = sbase + (uint32_t)s * STAGE;
        #pragma unroll 2
        for (int id = tid; id < NCH; id += 256) {
            uint32_t dst; const __half* src;
            if (id < NCHA) {
                const int p = id / (128 * CPR);
                const int rem = id - p * 128 * CPR;
                const int r = rem / CPR, c = rem - r * CPR;
                dst = sb0 + (uint32_t)(p * APL + r * BKB + swz(c, r) * 16);
                src = A + (size_t)p * aPl + (size_t)(m0 + r) * KDIM + k0 + c * 8;
            } else {
                const int id2 = id - NCHA;
                const int p = id2 / (64 * CPR);
                const int rem = id2 - p * 64 * CPR;
                const int r = rem / CPR, c = rem - r * CPR;
                dst = sb0 + (uint32_t)(P * APL + p * BPL + r * BKB + swz(c, r) * 16);
                src = Bp + (size_t)p * bPl + (size_t)(brow0 + r) * KDIM + k0 + c * 8;
            }
            asm volatile("cp.async.cg.shared.global [%0], [%1], 16;\n"
                         :: "r"(dst), "l"(src));
        }
        asm volatile("cp.async.commit_group;\n" ::: "memory");
    };

    const int rg = ((l >> 3) & 1) * 8 + (l & 7);
    const int ch = l >> 4;

    issue(0);
    issue(1);
    for (int i = 0; i < NIT; i++) {
        asm volatile("cp.async.wait_group 1;\n" ::: "memory");
        __syncthreads();
        const uint32_t sb0 = sbase + (uint32_t)(i & 1) * STAGE;

        #pragma unroll
        for (int ps = 0; ps < NPAS; ps++) {
            const int PA3[3] = {0, 0, 1}, PB3[3] = {0, 1, 0};
            const int pa = PA3[ps], pb = PB3[ps];
            #pragma unroll
            for (int kt = 0; kt < KT; kt++) {
                uint32_t af[2][4];
                #pragma unroll
                for (int mt = 0; mt < 2; mt++) {
                    const int row = wm + mt * 16 + rg;
                    const int c = kt * 2 + ch;
                    const uint32_t ad = sb0 + (uint32_t)(pa * APL + row * BKB + swz(c, row) * 16);
                    asm volatile("ldmatrix.sync.aligned.m8n8.x4.shared.b16 {%0,%1,%2,%3}, [%4];\n"
                        : "=r"(af[mt][0]), "=r"(af[mt][1]), "=r"(af[mt][2]), "=r"(af[mt][3])
                        : "r"(ad));
                }
                uint32_t bfr[4][2];
                #pragma unroll
                for (int np = 0; np < 2; np++) {
                    const int row = wn + np * 16 + rg;
                    const int c = kt * 2 + ch;
                    const uint32_t ad = sb0 + (uint32_t)(P * APL + pb * BPL + row * BKB + swz(c, row) * 16);
                    uint32_t b0, b1, b2, b3;
                    asm volatile("ldmatrix.sync.aligned.m8n8.x4.shared.b16 {%0,%1,%2,%3}, [%4];\n"
                        : "=r"(b0), "=r"(b1), "=r"(b2), "=r"(b3) : "r"(ad));
                    bfr[np * 2 + 0][0] = b0; bfr[np * 2 + 0][1] = b2;
                    bfr[np * 2 + 1][0] = b1; bfr[np * 2 + 1][1] = b3;
                }
                #pragma unroll
                for (int mt = 0; mt < 2; mt++)
                    #pragma unroll
                    for (int nt = 0; nt < 4; nt++)
                        asm volatile(
                            "mma.sync.aligned.m16n8k16.row.col.f32.f16.f16.f32 "
                            "{%0,%1,%2,%3}, {%4,%5,%6,%7}, {%8,%9}, {%0,%1,%2,%3};\n"
                            : "+f"(acc[mt][nt][0]), "+f"(acc[mt][nt][1]),
                              "+f"(acc[mt][nt][2]), "+f"(acc[mt][nt][3])
                            : "r"(af[mt][0]), "r"(af[mt][1]), "r"(af[mt][2]), "r"(af[mt][3]),
                              "r"(bfr[nt][0]), "r"(bfr[nt][1]));
            }
        }
        __syncthreads();
        if (i + 2 < NIT) issue(i + 2);
        else asm volatile("cp.async.commit_group;\n" ::: "memory");
    }

    float* Cb = seg1 ? C1 : C2;
    const int ldc = seg1 ? ld1 : ld2;
    const int col0 = seg1 ? n0 : (n0 - n1);
    #pragma unroll
    for (int mt = 0; mt < 2; mt++) {
        const int row = m0 + wm + mt * 16 + (l >> 2);
        #pragma unroll
        for (int nt = 0; nt < 4; nt++) {
            const int cc = wn + nt * 8 + (l & 3) * 2;
            float b0 = 0.f, b1 = 0.f;
            if (bias && seg1) { b0 = bias[n0 + cc]; b1 = bias[n0 + cc + 1]; }
            *(float2*)(Cb + (size_t)row * ldc + col0 + cc) =
                make_float2(acc[mt][nt][0] * oscale + b0, acc[mt][nt][1] * oscale + b1);
            *(float2*)(Cb + (size_t)(row + 8) * ldc + col0 + cc) =
                make_float2(acc[mt][nt][2] * oscale + b0, acc[mt][nt][3] * oscale + b1);
        }
    }
}

// ---------------- one fused conversion kernel ---------------------------------
// grid: [0,4096) hidden (unscaled) | [4096,8192) down (x64)
//       [8192,10240) Wq^T (x64)    | [10240,11264) up^T (x64)
__global__ __launch_bounds__(256)
void conv_all(const float* __restrict__ hidden, const float* __restrict__ Wq,
              const float* __restrict__ down, const float* __restrict__ up,
              __half* __restrict__ hid, __half* __restrict__ wqT,
              __half* __restrict__ dwn, __half* __restrict__ upT)
{
    const int b = blockIdx.x;
    const int tid = threadIdx.x;
    if (b < 8192) {
        const bool isH = (b < 4096);
        const int i = (isH ? b : b - 4096) * 256 + tid;
        const float v = isH ? hidden[i] : down[i] * WSCALE;
        const __half h = __float2half(v);
        const __half lo = __float2half(v - __half2float(h));
        if (isH) { hid[i] = h; hid[TOK * D + i] = lo; }
        else     { dwn[i] = h; dwn[E * D + i] = lo; }
    } else {
        __shared__ float t[32][33];
        const bool isW = (b < 10240);
        const int idx = isW ? (b - 8192) : (b - 10240);
        const int N = isW ? HQ : O;
        const int nb = N / 32;
        const int nx = (idx % nb) * 32, ky = (idx / nb) * 32;
        const int tx = tid & 31, ty = tid >> 5;   // 32 x 8
        const float* in = isW ? Wq : up;
        #pragma unroll
        for (int j = 0; j < 32; j += 8)
            t[ty + j][tx] = in[(size_t)(ky + ty + j) * N + nx + tx];
        __syncthreads();
        #pragma unroll
        for (int j = 0; j < 32; j += 8) {
            const int n = nx + ty + j;
            const int k = ky + tx;
            const float v = t[tx][ty + j] * WSCALE;
            const __half h = __float2half(v);
            const __half lo = __float2half(v - __half2float(h));
            if (isW) {
                wqT[(size_t)n * KDIM + k] = h;
                wqT[HQ * D + (size_t)n * KDIM + k] = lo;
            } else {
                upT[(size_t)n * KDIM + k] = h;
                upT[O * E + (size_t)n * KDIM + k] = lo;
            }
        }
    }
}

// ---------------- norm keys + zero stats (one launch) --------------------------
__global__ __launch_bounds__(128)
void norm_keys_zero_kernel(const float* __restrict__ k0,
                           const float* __restrict__ k1) {
    const int row = blockIdx.x;
    const int tid = threadIdx.x;
    if (row == 2 * NK) {
        g_sums[tid] = 0.f; g_sums[tid + 128] = 0.f;
        g_sqs[tid] = 0.f;  g_sqs[tid + 128] = 0.f;
        return;
    }
    const float* src = (row < NK) ? (k0 + (size_t)row * HALF)
                                  : (k1 + (size_t)(row - NK) * HALF);
    float* dst = (row < NK) ? (g_k0n + (size_t)row * HALF)
                            : (g_k1n + (size_t)(row - NK) * HALF);
    __shared__ float red[128];
    float v = src[tid];
    red[tid] = v * v;
    __syncthreads();
    for (int s = 64; s > 0; s >>= 1) {
        if (tid < s) red[tid] += red[tid + s];
        __syncthreads();
    }
    float n = sqrtf(red[0]);
    dst[tid] = v / fmaxf(n, 1e-12f);
}

// ---------------- BN partial sums: 512 blocks x 2 rows -------------------------
__global__ __launch_bounds__(256)
void stats_partial_kernel() {
    const int tid = threadIdx.x;
    const int rowStart = blockIdx.x * 2;
    float s = 0.f, sq = 0.f;
    #pragma unroll
    for (int r = 0; r < 2; r++) {
        const float* row = g_q + (size_t)(rowStart + r) * HQ;
        #pragma unroll
        for (int h = 0; h < HEADS; h++) {
            float v = row[h * QD + tid];
            s += v; sq += v * v;
        }
    }
    atomicAdd(&g_sums[tid], s);
    atomicAdd(&g_sqs[tid], sq);
}

// ---------------- score: BN(from raw sums) + L2norm + dots + top4x4 + softmax --
__global__ __launch_bounds__(128)
void score_kernel(const float* __restrict__ gamma,
                  const float* __restrict__ beta) {
    const int u = blockIdx.x;
    const int t = u >> 3;
    const int h = u & 7;
    const int tid = threadIdx.x;

    __shared__ float q0[HALF], q1[HALF];
    __shared__ float red0[128], red1[128];
    __shared__ float s0s[NK], s1s[NK];
    __shared__ float ts0[DTK], ts1[DTK];
    __shared__ int   ti0[DTK], ti1[DTK];
    __shared__ float combS[16];
    __shared__ int   combI[16];
    __shared__ float smx, ssum;

    const float invN = 1.0f / (float)(TOK * HEADS);
    const float* qrow = g_q + (size_t)t * HQ + h * QD;
    float a = qrow[tid];
    float b = qrow[HALF + tid];
    {
        const float m0v = g_sums[tid] * invN;
        const float v0 = g_sqs[tid] * invN - m0v * m0v;
        const float m1v = g_sums[HALF + tid] * invN;
        const float v1 = g_sqs[HALF + tid] * invN - m1v * m1v;
        a = (a - m0v) * rsqrtf(v0 + 1e-5f) * gamma[tid] + beta[tid];
        b = (b - m1v) * rsqrtf(v1 + 1e-5f) * gamma[HALF + tid] + beta[HALF + tid];
    }

    red0[tid] = a * a;
    red1[tid] = b * b;
    __syncthreads();
    for (int s = 64; s > 0; s >>= 1) {
        if (tid < s) { red0[tid] += red0[tid + s]; red1[tid] += red1[tid + s]; }
        __syncthreads();
    }
    float n0 = fmaxf(sqrtf(red0[0]), 1e-12f);
    float n1 = fmaxf(sqrtf(red1[0]), 1e-12f);
    q0[tid] = a / n0;
    q1[tid] = b / n1;
    __syncthreads();

    const int w = tid >> 5, l = tid & 31;
    for (int j = w; j < NK; j += 4) {
        const float* kr0 = g_k0n + j * HALF;
        const float* kr1 = g_k1n + j * HALF;
        float d0 = kr0[l] * q0[l] + kr0[l + 32] * q0[l + 32]
                 + kr0[l + 64] * q0[l + 64] + kr0[l + 96] * q0[l + 96];
        float d1 = kr1[l] * q1[l] + kr1[l + 32] * q1[l + 32]
                 + kr1[l + 64] * q1[l + 64] + kr1[l + 96] * q1[l + 96];
        #pragma unroll
        for (int off = 16; off; off >>= 1) {
            d0 += __shfl_down_sync(0xffffffffu, d0, off);
            d1 += __shfl_down_sync(0xffffffffu, d1, off);
        }
        if (l == 0) { s0s[j] = d0; s1s[j] = d1; }
    }
    __syncthreads();

    // warp-parallel top-4 per axis (ties -> lowest index, matching lax.top_k)
    if (w < 2) {
        float v = (w == 0) ? s0s[l] : s1s[l];
        #pragma unroll
        for (int p = 0; p < DTK; p++) {
            float bv = v; int bi = l;
            #pragma unroll
            for (int off = 16; off; off >>= 1) {
                float ov = __shfl_down_sync(0xffffffffu, bv, off);
                int oi = __shfl_down_sync(0xffffffffu, bi, off);
                if (ov > bv || (ov == bv && oi < bi)) { bv = ov; bi = oi; }
            }
            bv = __shfl_sync(0xffffffffu, bv, 0);
            bi = __shfl_sync(0xffffffffu, bi, 0);
            if (l == 0) {
                if (w == 0) { ts0[p] = bv; ti0[p] = bi; }
                else        { ts1[p] = bv; ti1[p] = bi; }
            }
            if (l == bi) v = -1e30f;
        }
    }
    __syncthreads();

    if (tid < 16) {
        int i = tid >> 2, j = tid & 3;
        combS[tid] = ts0[i] + ts1[j];
        combI[tid] = ti0[i] * NK + ti1[j];
    }
    __syncthreads();
    if (tid == 0) {
        float m = -1e30f;
        for (int k = 0; k < 16; k++) m = fmaxf(m, combS[k]);
        float s = 0.f;
        for (int k = 0; k < 16; k++) s += expf(combS[k] - m);
        smx = m; ssum = s;
    }
    __syncthreads();
    if (tid < 16) {
        g_idx[(size_t)u * 16 + tid] = (unsigned short)combI[tid];
        g_w[(size_t)u * 16 + tid]   = expf(combS[tid] - smx) / ssum;
    }
}

// ---------------- eh -> C fp16 planes (gelu * softmax weight, scattered) ------
__global__ __launch_bounds__(256)
void transformC_kernel(__half* __restrict__ c0, __half* __restrict__ c1) {
    __shared__ float acc[E];
    const int t = blockIdx.x;
    const int tid = threadIdx.x;
    for (int i = tid; i < E; i += 256) acc[i] = 0.f;
    __syncthreads();
    if (tid < NEXP) {
        const int idx = (int)g_idx[(size_t)t * NEXP + tid];
        const float v = g_eh[(size_t)t * E + idx];
        const float g = 0.5f * v * (1.0f + erff(v * 0.70710678118654752f));
        atomicAdd(&acc[idx], g * g_w[(size_t)t * NEXP + tid]);
    }
    __syncthreads();
    for (int i = tid; i < E; i += 256) {
        const float v = acc[i];
        const __half h = __float2half(v);
        c0[(size_t)t * E + i] = h;
        c1[(size_t)t * E + i] = __float2half(v - __half2float(h));
    }
}

// ---------------- launch -------------------------------------------------------
extern "C" void kernel_launch(void* const* d_in, const int* in_sizes, int n_in,
                              void* d_out, int out_size) {
    const float* hidden = (const float*)d_in[0];   // [2,512,1024]
    const float* Wq     = (const float*)d_in[1];   // [1024,2048]
    const float* bq     = (const float*)d_in[2];   // [2048]
    const float* gamma  = (const float*)d_in[3];   // [256]
    const float* beta   = (const float*)d_in[4];   // [256]
    const float* k0     = (const float*)d_in[5];   // [32,128]
    const float* k1     = (const float*)d_in[6];   // [32,128]
    const float* down   = (const float*)d_in[7];   // [1024,1024]
    const float* up     = (const float*)d_in[8];   // [1024,1024]
    float* out = (float*)d_out;                    // [2,512,1024]

    float *qbuf = nullptr, *ehf = nullptr;
    __half *hid = nullptr, *wqT = nullptr, *dwn = nullptr, *upT = nullptr;
    cudaGetSymbolAddress((void**)&qbuf, g_q);
    cudaGetSymbolAddress((void**)&ehf, g_eh);
    cudaGetSymbolAddress((void**)&hid, g_hid);
    cudaGetSymbolAddress((void**)&wqT, g_wqT);
    cudaGetSymbolAddress((void**)&dwn, g_dwn);
    cudaGetSymbolAddress((void**)&upT, g_upT);
    __half* cp0 = (__half*)(qbuf + TOK * E);   // high 4MB of g_q (dead after score)
    __half* cp1 = cp0 + TOK * E;

    conv_all<<<11264, 256>>>(hidden, Wq, down, up, hid, wqT, dwn, upT);
    norm_keys_zero_kernel<<<2 * NK + 1, 128>>>(k0, k1);

    // merged GEMM: [q | eh] = hid @ [wqT | dwn]^T  (384 CTAs = 1.3 full waves)
    gemm_planes<<<dim3((HQ + E) / 64, TOK / 128), 256>>>(
        hid, wqT, dwn, bq, qbuf, ehf,
        HQ, HQ, E, TOK * D, HQ * D, E * D, IWSCALE);

    stats_partial_kernel<<<512, 256>>>();
    score_kernel<<<TOK * HEADS, 128>>>(gamma, beta);

    // eh -> C fp16 planes (gelu * softmax weight, scattered)
    transformC_kernel<<<TOK, 256>>>(cp0, cp1);

    // out = C @ up (degenerate split: single segment)
    gemm_planes<<<dim3(O / 64, TOK / 128), 256>>>(
        cp0, upT, upT, nullptr, out, out,
        O, O, O, TOK * E, O * E, O * E, IWSCALE);
}

// round 17
// speedup vs baseline: 1.0153x; 1.0153x over previous
#include <cuda_runtime.h>
#include <cuda_fp16.h>
#include <math.h>
#include <stdint.h>

// ---------------- problem constants -----------------------------------------
#define TOK   1024
#define D     1024
#define HQ    2048
#define HEADS 8
#define QD    256
#define HALF  128
#define NK    32
#define DTK   4
#define NEXP  128
#define E     1024
#define O     1024
#define KDIM  1024
#define WSCALE   64.0f
#define IWSCALE  (1.0f / 64.0f)

// ---------------- scratch (~33 MB of __device__ globals) ----------------------
__device__ __align__(256) float g_q[TOK * HQ];          // 8MB; high 4MB -> C planes
__device__ __align__(256) float g_eh[TOK * E];          // 4MB dense expert pre-acts
__device__ __align__(256) __half g_hid[2 * TOK * D];    // 4MB  (h,l planes)
__device__ __align__(256) __half g_wqT[2 * HQ * D];     // 8MB  (transposed, x64)
__device__ __align__(256) __half g_dwn[2 * E * D];      // 4MB  (x64)
__device__ __align__(256) __half g_upT[2 * O * E];      // 4MB  (transposed, x64)
__device__ float g_sums[QD];
__device__ float g_sqs[QD];
__device__ float g_k0n[NK * HALF];   // column-major: [elem*32 + key]
__device__ float g_k1n[NK * HALF];
__device__ unsigned short g_idx[TOK * NEXP];
__device__ float g_w[TOK * NEXP];

// ---------------- helpers ----------------------------------------------------
__device__ __forceinline__ uint32_t s2u(const void* p) {
    uint32_t r;
    asm("{ .reg .u64 t; cvta.to.shared.u64 t, %1; cvt.u32.u64 %0, t; }"
        : "=r"(r) : "l"(p));
    return r;
}

// ---------------- fp16 2-plane split warp-MMA GEMM (segmented N) --------------
#define P    2
#define NPAS 3
#define BK   32
__global__ __launch_bounds__(256, 2)
void gemm_planes(const __half* __restrict__ A,
                 const __half* __restrict__ B1, const __half* __restrict__ B2,
                 const float* __restrict__ bias,
                 float* __restrict__ C1, float* __restrict__ C2,
                 int n1, int ld1, int ld2,
                 int aPl, int b1Pl, int b2Pl, float oscale)
{
    constexpr int CPR   = BK / 8;
    constexpr int BKB   = BK * 2;
    constexpr int APL   = 128 * BKB;
    constexpr int BPL   = 64 * BKB;
    constexpr int STAGE = P * (APL + BPL);   // 24KB
    constexpr int NCHA  = P * 128 * CPR;
    constexpr int NCH   = NCHA + P * 64 * CPR;
    constexpr int NIT   = KDIM / BK;
    constexpr int KT    = BK / 16;

    __shared__ __align__(1024) char smem[2 * STAGE];   // 48KB static
    const uint32_t sbase = s2u(smem);
    const int tid = threadIdx.x, w = tid >> 5, l = tid & 31;
    const int m0 = blockIdx.y * 128, n0 = blockIdx.x * 64;
    const int wm = (w >> 1) * 32, wn = (w & 1) * 32;

    const bool seg1 = (n0 < n1);
    const __half* Bp = seg1 ? B1 : B2;
    const int brow0 = seg1 ? n0 : (n0 - n1);
    const int bPl = seg1 ? b1Pl : b2Pl;

    float acc[2][4][4];
    #pragma unroll
    for (int a = 0; a < 2; a++)
        #pragma unroll
        for (int b = 0; b < 4; b++)
            #pragma unroll
            for (int c = 0; c < 4; c++) acc[a][b][c] = 0.f;

    auto swz = [](int c, int r) -> int { return c ^ ((r >> 1) & 3); };

    auto issue = [&](int it) {
        const int s = it & 1;
        const int k0 = it * BK;
        const uint32_t sb0 = sbase + (uint32_t)s * STAGE;
        #pragma unroll 2
        for (int id = tid; id < NCH; id += 256) {
            uint32_t dst; const __half* src;
            if (id < NCHA) {
                const int p = id / (128 * CPR);
                const int rem = id - p * 128 * CPR;
                const int r = rem / CPR, c = rem - r * CPR;
                dst = sb0 + (uint32_t)(p * APL + r * BKB + swz(c, r) * 16);
                src = A + (size_t)p * aPl + (size_t)(m0 + r) * KDIM + k0 + c * 8;
            } else {
                const int id2 = id - NCHA;
                const int p = id2 / (64 * CPR);
                const int rem = id2 - p * 64 * CPR;
                const int r = rem / CPR, c = rem - r * CPR;
                dst = sb0 + (uint32_t)(P * APL + p * BPL + r * BKB + swz(c, r) * 16);
                src = Bp + (size_t)p * bPl + (size_t)(brow0 + r) * KDIM + k0 + c * 8;
            }
            asm volatile("cp.async.cg.shared.global [%0], [%1], 16;\n"
                         :: "r"(dst), "l"(src));
        }
        asm volatile("cp.async.commit_group;\n" ::: "memory");
    };

    const int rg = ((l >> 3) & 1) * 8 + (l & 7);
    const int ch = l >> 4;

    issue(0);
    issue(1);
    for (int i = 0; i < NIT; i++) {
        asm volatile("cp.async.wait_group 1;\n" ::: "memory");
        __syncthreads();
        const uint32_t sb0 = sbase + (uint32_t)(i & 1) * STAGE;

        #pragma unroll
        for (int ps = 0; ps < NPAS; ps++) {
            const int PA3[3] = {0, 0, 1}, PB3[3] = {0, 1, 0};
            const int pa = PA3[ps], pb = PB3[ps];
            #pragma unroll
            for (int kt = 0; kt < KT; kt++) {
                uint32_t af[2][4];
                #pragma unroll
                for (int mt = 0; mt < 2; mt++) {
                    const int row = wm + mt * 16 + rg;
                    const int c = kt * 2 + ch;
                    const uint32_t ad = sb0 + (uint32_t)(pa * APL + row * BKB + swz(c, row) * 16);
                    asm volatile("ldmatrix.sync.aligned.m8n8.x4.shared.b16 {%0,%1,%2,%3}, [%4];\n"
                        : "=r"(af[mt][0]), "=r"(af[mt][1]), "=r"(af[mt][2]), "=r"(af[mt][3])
                        : "r"(ad));
                }
                uint32_t bfr[4][2];
                #pragma unroll
                for (int np = 0; np < 2; np++) {
                    const int row = wn + np * 16 + rg;
                    const int c = kt * 2 + ch;
                    const uint32_t ad = sb0 + (uint32_t)(P * APL + pb * BPL + row * BKB + swz(c, row) * 16);
                    uint32_t b0, b1, b2, b3;
                    asm volatile("ldmatrix.sync.aligned.m8n8.x4.shared.b16 {%0,%1,%2,%3}, [%4];\n"
                        : "=r"(b0), "=r"(b1), "=r"(b2), "=r"(b3) : "r"(ad));
                    bfr[np * 2 + 0][0] = b0; bfr[np * 2 + 0][1] = b2;
                    bfr[np * 2 + 1][0] = b1; bfr[np * 2 + 1][1] = b3;
                }
                #pragma unroll
                for (int mt = 0; mt < 2; mt++)
                    #pragma unroll
                    for (int nt = 0; nt < 4; nt++)
                        asm volatile(
                            "mma.sync.aligned.m16n8k16.row.col.f32.f16.f16.f32 "
                            "{%0,%1,%2,%3}, {%4,%5,%6,%7}, {%8,%9}, {%0,%1,%2,%3};\n"
                            : "+f"(acc[mt][nt][0]), "+f"(acc[mt][nt][1]),
                              "+f"(acc[mt][nt][2]), "+f"(acc[mt][nt][3])
                            : "r"(af[mt][0]), "r"(af[mt][1]), "r"(af[mt][2]), "r"(af[mt][3]),
                              "r"(bfr[nt][0]), "r"(bfr[nt][1]));
            }
        }
        __syncthreads();
        if (i + 2 < NIT) issue(i + 2);
        else asm volatile("cp.async.commit_group;\n" ::: "memory");
    }

    float* Cb = seg1 ? C1 : C2;
    const int ldc = seg1 ? ld1 : ld2;
    const int col0 = seg1 ? n0 : (n0 - n1);
    #pragma unroll
    for (int mt = 0; mt < 2; mt++) {
        const int row = m0 + wm + mt * 16 + (l >> 2);
        #pragma unroll
        for (int nt = 0; nt < 4; nt++) {
            const int cc = wn + nt * 8 + (l & 3) * 2;
            float b0 = 0.f, b1 = 0.f;
            if (bias && seg1) { b0 = bias[n0 + cc]; b1 = bias[n0 + cc + 1]; }
            *(float2*)(Cb + (size_t)row * ldc + col0 + cc) =
                make_float2(acc[mt][nt][0] * oscale + b0, acc[mt][nt][1] * oscale + b1);
            *(float2*)(Cb + (size_t)(row + 8) * ldc + col0 + cc) =
                make_float2(acc[mt][nt][2] * oscale + b0, acc[mt][nt][3] * oscale + b1);
        }
    }
}

// ---------------- one fused conversion kernel ---------------------------------
__global__ __launch_bounds__(256)
void conv_all(const float* __restrict__ hidden, const float* __restrict__ Wq,
              const float* __restrict__ down, const float* __restrict__ up,
              __half* __restrict__ hid, __half* __restrict__ wqT,
              __half* __restrict__ dwn, __half* __restrict__ upT)
{
    const int b = blockIdx.x;
    const int tid = threadIdx.x;
    if (b < 8192) {
        const bool isH = (b < 4096);
        const int i = (isH ? b : b - 4096) * 256 + tid;
        const float v = isH ? hidden[i] : down[i] * WSCALE;
        const __half h = __float2half(v);
        const __half lo = __float2half(v - __half2float(h));
        if (isH) { hid[i] = h; hid[TOK * D + i] = lo; }
        else     { dwn[i] = h; dwn[E * D + i] = lo; }
    } else {
        __shared__ float t[32][33];
        const bool isW = (b < 10240);
        const int idx = isW ? (b - 8192) : (b - 10240);
        const int N = isW ? HQ : O;
        const int nb = N / 32;
        const int nx = (idx % nb) * 32, ky = (idx / nb) * 32;
        const int tx = tid & 31, ty = tid >> 5;
        const float* in = isW ? Wq : up;
        #pragma unroll
        for (int j = 0; j < 32; j += 8)
            t[ty + j][tx] = in[(size_t)(ky + ty + j) * N + nx + tx];
        __syncthreads();
        #pragma unroll
        for (int j = 0; j < 32; j += 8) {
            const int n = nx + ty + j;
            const int k = ky + tx;
            const float v = t[tx][ty + j] * WSCALE;
            const __half h = __float2half(v);
            const __half lo = __float2half(v - __half2float(h));
            if (isW) {
                wqT[(size_t)n * KDIM + k] = h;
                wqT[HQ * D + (size_t)n * KDIM + k] = lo;
            } else {
                upT[(size_t)n * KDIM + k] = h;
                upT[O * E + (size_t)n * KDIM + k] = lo;
            }
        }
    }
}

// ---------------- norm keys (col-major out) + zero stats -----------------------
__global__ __launch_bounds__(128)
void norm_keys_zero_kernel(const float* __restrict__ k0,
                           const float* __restrict__ k1) {
    const int row = blockIdx.x;
    const int tid = threadIdx.x;
    if (row == 2 * NK) {
        g_sums[tid] = 0.f; g_sums[tid + 128] = 0.f;
        g_sqs[tid] = 0.f;  g_sqs[tid + 128] = 0.f;
        return;
    }
    const float* src = (row < NK) ? (k0 + (size_t)row * HALF)
                                  : (k1 + (size_t)(row - NK) * HALF);
    float* dst = (row < NK) ? g_k0n : g_k1n;
    const int key = (row < NK) ? row : (row - NK);
    __shared__ float red[128];
    float v = src[tid];
    red[tid] = v * v;
    __syncthreads();
    for (int s = 64; s > 0; s >>= 1) {
        if (tid < s) red[tid] += red[tid + s];
        __syncthreads();
    }
    float n = sqrtf(red[0]);
    dst[tid * NK + key] = v / fmaxf(n, 1e-12f);   // column-major [elem*32+key]
}

// ---------------- BN partial sums: 128 blocks x 8 rows (proven 6.3us) ----------
__global__ __launch_bounds__(256)
void stats_partial_kernel() {
    const int tid = threadIdx.x;
    const int rowStart = blockIdx.x * 8;
    float s = 0.f, sq = 0.f;
    #pragma unroll
    for (int r = 0; r < 8; r++) {
        const float* row = g_q + (size_t)(rowStart + r) * HQ;
        #pragma unroll
        for (int h = 0; h < HEADS; h++) {
            float v = row[h * QD + tid];
            s += v; sq += v * v;
        }
    }
    atomicAdd(&g_sums[tid], s);
    atomicAdd(&g_sqs[tid], sq);
}

// ---------------- score: warp-per-unit, shared keys, shuffle-only --------------
// 1024 blocks x 256 thr; 8 warps = 8 (token,head) units. One __syncthreads
// (key staging); everything after is warp-local.
__global__ __launch_bounds__(256)
void score_kernel(const float* __restrict__ gamma,
                  const float* __restrict__ beta) {
    __shared__ float k0s[NK * HALF];   // col-major [i*32+j]
    __shared__ float k1s[NK * HALF];
    __shared__ float q0s[8][HALF];
    __shared__ float q1s[8][HALF];

    const int tid = threadIdx.x, w = tid >> 5, l = tid & 31;
    for (int i = tid; i < NK * HALF; i += 256) {
        k0s[i] = g_k0n[i];
        k1s[i] = g_k1n[i];
    }
    __syncthreads();

    const int u = blockIdx.x * 8 + w;
    const int t = u >> 3, h = u & 7;
    const float invN = 1.0f / (float)(TOK * HEADS);
    const float* qrow = g_q + (size_t)t * HQ + h * QD;

    // 8 q elements per lane, BN applied inline
    float vals[8];
    {
        float4 va = *(const float4*)(qrow + l * 8);
        float4 vb = *(const float4*)(qrow + l * 8 + 4);
        vals[0] = va.x; vals[1] = va.y; vals[2] = va.z; vals[3] = va.w;
        vals[4] = vb.x; vals[5] = vb.y; vals[6] = vb.z; vals[7] = vb.w;
    }
    float ss = 0.f;
    #pragma unroll
    for (int j = 0; j < 8; j++) {
        const int col = l * 8 + j;
        const float m = g_sums[col] * invN;
        const float var = g_sqs[col] * invN - m * m;
        vals[j] = (vals[j] - m) * rsqrtf(var + 1e-5f) * gamma[col] + beta[col];
        ss += vals[j] * vals[j];
    }
    // butterfly within each 16-lane half (offsets closed under each half)
    #pragma unroll
    for (int off = 8; off; off >>= 1) ss += __shfl_xor_sync(0xffffffffu, ss, off);
    const float inv = 1.0f / fmaxf(sqrtf(ss), 1e-12f);
    {
        float* qs = (l < 16) ? &q0s[w][l * 8] : &q1s[w][(l - 16) * 8];
        #pragma unroll
        for (int j = 0; j < 8; j++) qs[j] = vals[j] * inv;
    }
    __syncwarp();

    // dots: lane l <-> key l (conflict-free: consecutive lanes, consecutive banks)
    float s0 = 0.f, s1 = 0.f;
    #pragma unroll 8
    for (int i = 0; i < HALF; i++) {
        s0 = fmaf(k0s[i * NK + l], q0s[w][i], s0);
        s1 = fmaf(k1s[i * NK + l], q1s[w][i], s1);
    }

    // warp top-4 per axis (ties -> lowest index, matching lax.top_k)
    float ts0a[DTK], ts1a[DTK];
    int   ti0a[DTK], ti1a[DTK];
    float v0 = s0, v1 = s1;
    #pragma unroll
    for (int p = 0; p < DTK; p++) {
        float bv = v0; int bi = l;
        #pragma unroll
        for (int off = 16; off; off >>= 1) {
            float ov = __shfl_down_sync(0xffffffffu, bv, off);
            int oi = __shfl_down_sync(0xffffffffu, bi, off);
            if (ov > bv || (ov == bv && oi < bi)) { bv = ov; bi = oi; }
        }
        bv = __shfl_sync(0xffffffffu, bv, 0);
        bi = __shfl_sync(0xffffffffu, bi, 0);
        ts0a[p] = bv; ti0a[p] = bi;
        if (l == bi) v0 = -1e30f;

        float cv = v1; int ci = l;
        #pragma unroll
        for (int off = 16; off; off >>= 1) {
            float ov = __shfl_down_sync(0xffffffffu, cv, off);
            int oi = __shfl_down_sync(0xffffffffu, ci, off);
            if (ov > cv || (ov == cv && oi < ci)) { cv = ov; ci = oi; }
        }
        cv = __shfl_sync(0xffffffffu, cv, 0);
        ci = __shfl_sync(0xffffffffu, ci, 0);
        ts1a[p] = cv; ti1a[p] = ci;
        if (l == ci) v1 = -1e30f;
    }

    // cartesian combine on lanes 0..15 (constant-index selects, no spills)
    const int ii = l >> 2, jj = l & 3;
    float cA = (ii == 0) ? ts0a[0] : (ii == 1) ? ts0a[1] : (ii == 2) ? ts0a[2] : ts0a[3];
    int   iA = (ii == 0) ? ti0a[0] : (ii == 1) ? ti0a[1] : (ii == 2) ? ti0a[2] : ti0a[3];
    float cB = (jj == 0) ? ts1a[0] : (jj == 1) ? ts1a[1] : (jj == 2) ? ts1a[2] : ts1a[3];
    int   iB = (jj == 0) ? ti1a[0] : (jj == 1) ? ti1a[1] : (jj == 2) ? ti1a[2] : ti1a[3];
    float cs = (l < 16) ? (cA + cB) : -1e30f;

    // softmax over the low 16 lanes (xor offsets 8,4,2,1 stay within each half)
    float mx = cs;
    #pragma unroll
    for (int off = 8; off; off >>= 1) mx = fmaxf(mx, __shfl_xor_sync(0xffffffffu, mx, off));
    float e = (l < 16) ? expf(cs - mx) : 0.f;
    float sm = e;
    #pragma unroll
    for (int off = 8; off; off >>= 1) sm += __shfl_xor_sync(0xffffffffu, sm, off);

    if (l < 16) {
        g_idx[(size_t)u * 16 + l] = (unsigned short)(iA * NK + iB);
        g_w[(size_t)u * 16 + l] = e / sm;
    }
}

// ---------------- eh -> C fp16 planes (gelu * softmax weight, scattered) ------
__global__ __launch_bounds__(256)
void transformC_kernel(__half* __restrict__ c0, __half* __restrict__ c1) {
    __shared__ float acc[E];
    const int t = blockIdx.x;
    const int tid = threadIdx.x;
    for (int i = tid; i < E; i += 256) acc[i] = 0.f;
    __syncthreads();
    if (tid < NEXP) {
        const int idx = (int)g_idx[(size_t)t * NEXP + tid];
        const float v = g_eh[(size_t)t * E + idx];
        const float g = 0.5f * v * (1.0f + erff(v * 0.70710678118654752f));
        atomicAdd(&acc[idx], g * g_w[(size_t)t * NEXP + tid]);
    }
    __syncthreads();
    for (int i = tid; i < E; i += 256) {
        const float v = acc[i];
        const __half h = __float2half(v);
        c0[(size_t)t * E + i] = h;
        c1[(size_t)t * E + i] = __float2half(v - __half2float(h));
    }
}

// ---------------- launch -------------------------------------------------------
extern "C" void kernel_launch(void* const* d_in, const int* in_sizes, int n_in,
                              void* d_out, int out_size) {
    const float* hidden = (const float*)d_in[0];   // [2,512,1024]
    const float* Wq     = (const float*)d_in[1];   // [1024,2048]
    const float* bq     = (const float*)d_in[2];   // [2048]
    const float* gamma  = (const float*)d_in[3];   // [256]
    const float* beta   = (const float*)d_in[4];   // [256]
    const float* k0     = (const float*)d_in[5];   // [32,128]
    const float* k1     = (const float*)d_in[6];   // [32,128]
    const float* down   = (const float*)d_in[7];   // [1024,1024]
    const float* up     = (const float*)d_in[8];   // [1024,1024]
    float* out = (float*)d_out;                    // [2,512,1024]

    float *qbuf = nullptr, *ehf = nullptr;
    __half *hid = nullptr, *wqT = nullptr, *dwn = nullptr, *upT = nullptr;
    cudaGetSymbolAddress((void**)&qbuf, g_q);
    cudaGetSymbolAddress((void**)&ehf, g_eh);
    cudaGetSymbolAddress((void**)&hid, g_hid);
    cudaGetSymbolAddress((void**)&wqT, g_wqT);
    cudaGetSymbolAddress((void**)&dwn, g_dwn);
    cudaGetSymbolAddress((void**)&upT, g_upT);
    __half* cp0 = (__half*)(qbuf + TOK * E);   // high 4MB of g_q (dead after score)
    __half* cp1 = cp0 + TOK * E;

    conv_all<<<11264, 256>>>(hidden, Wq, down, up, hid, wqT, dwn, upT);
    norm_keys_zero_kernel<<<2 * NK + 1, 128>>>(k0, k1);

    // merged GEMM: [q | eh] = hid @ [wqT | dwn]^T
    gemm_planes<<<dim3((HQ + E) / 64, TOK / 128), 256>>>(
        hid, wqT, dwn, bq, qbuf, ehf,
        HQ, HQ, E, TOK * D, HQ * D, E * D, IWSCALE);

    stats_partial_kernel<<<128, 256>>>();
    score_kernel<<<TOK * HEADS / 8, 256>>>(gamma, beta);

    // eh -> C fp16 planes (gelu * softmax weight, scattered)
    transformC_kernel<<<TOK, 256>>>(cp0, cp1);

    // out = C @ up (degenerate split: single segment)
    gemm_planes<<<dim3(O / 64, TOK / 128), 256>>>(
        cp0, upT, upT, nullptr, out, out,
        O, O, O, TOK * E, O * E, O * E, IWSCALE);
}